// round 15
// baseline (speedup 1.0000x reference)
#include <cuda_runtime.h>
#include <cstdint>

#define D_MODEL 1024
#define NHEAD   16
#define DK      64
#define BATCH   2
#define SEQ     2048
#define TOKENS  (BATCH * SEQ)   // 4096
#define NX4     (TOKENS * D_MODEL / 4)
#define NW4     (D_MODEL * D_MODEL / 4)

// ---------------- scratch (device globals; no allocations allowed) ----------
__device__ float g_Qh[BATCH * NHEAD * SEQ * DK];   // [B,H,S,dk] tf32-valued
__device__ float g_Kh[BATCH * NHEAD * SEQ * DK];   // [B,H,S,dk] tf32-valued
__device__ float g_Vh[BATCH * NHEAD * DK * SEQ];   // [B,H,dk,S] TRANSPOSED tf32
__device__ float g_ctx[TOKENS * D_MODEL];          // [B,S,D] tf32-valued
__device__ float g_X32[3 * TOKENS * D_MODEL];      // q,k,v tf32-rounded
__device__ float g_W32[4 * D_MODEL * D_MODEL];     // Wq,Wk,Wv,Wo tf32-rounded

// ============================================================================
// Helpers (plain sm_80-era PTX only)
// ============================================================================
__device__ __forceinline__ uint32_t smem_u32(const void* p) {
    uint32_t a;
    asm("{ .reg .u64 t; cvta.to.shared.u64 t, %1; cvt.u32.u64 %0, t; }" : "=r"(a) : "l"(p));
    return a;
}
__device__ __forceinline__ uint32_t f2tf32(float f) {
    uint32_t u;
    asm("cvt.rna.tf32.f32 %0, %1;" : "=r"(u) : "f"(f));
    return u;
}
__device__ __forceinline__ float tf32r(float f) { return __uint_as_float(f2tf32(f)); }

__device__ __forceinline__ void cp16(uint32_t dst, const void* src) {
    asm volatile("cp.async.cg.shared.global [%0], [%1], 16;" :: "r"(dst), "l"(src));
}
#define CP_COMMIT() asm volatile("cp.async.commit_group;" ::: "memory")
#define CP_WAIT0()  asm volatile("cp.async.wait_group 0;" ::: "memory")

__device__ __forceinline__ void mma_m16n8k8(float* d, const uint32_t* a, const uint32_t* b) {
    asm volatile(
        "mma.sync.aligned.m16n8k8.row.col.f32.tf32.tf32.f32 "
        "{%0,%1,%2,%3}, {%4,%5,%6,%7}, {%8,%9}, {%0,%1,%2,%3};"
        : "+f"(d[0]), "+f"(d[1]), "+f"(d[2]), "+f"(d[3])
        : "r"(a[0]), "r"(a[1]), "r"(a[2]), "r"(a[3]), "r"(b[0]), "r"(b[1]));
}
__device__ __forceinline__ void ldsm4(uint32_t* r, uint32_t a) {
    asm volatile("ldmatrix.sync.aligned.m8n8.x4.shared.b16 {%0,%1,%2,%3}, [%4];"
                 : "=r"(r[0]), "=r"(r[1]), "=r"(r[2]), "=r"(r[3]) : "r"(a));
}

// ============================================================================
// One-shot tf32 rounding of all GEMM inputs
// ============================================================================
__global__ __launch_bounds__(256) void cvt_tf32_kernel(
    const float* __restrict__ q,  const float* __restrict__ k,  const float* __restrict__ v,
    const float* __restrict__ Wq, const float* __restrict__ Wk,
    const float* __restrict__ Wv, const float* __restrict__ Wo)
{
    const int a = blockIdx.y;
    const float4* src; float4* dst; int n4;
    if (a < 3) {
        src = (const float4*)(a == 0 ? q : a == 1 ? k : v);
        dst = (float4*)(g_X32 + (size_t)a * TOKENS * D_MODEL);
        n4 = NX4;
    } else {
        src = (const float4*)(a == 3 ? Wq : a == 4 ? Wk : a == 5 ? Wv : Wo);
        dst = (float4*)(g_W32 + (size_t)(a - 3) * D_MODEL * D_MODEL);
        n4 = NW4;
    }
    for (int i = blockIdx.x * blockDim.x + threadIdx.x; i < n4; i += gridDim.x * blockDim.x) {
        float4 t = src[i];
        dst[i] = make_float4(tf32r(t.x), tf32r(t.y), tf32r(t.z), tf32r(t.w));
    }
}

// ============================================================================
// tf32 GEMM core: acc = A[m0:+128,:1024] @ B[n0:+128,:1024]^T
// BM=BN=128, BK=32, 256 threads, warp grid 2(m) x 4(n), warp tile 64x32.
// ============================================================================
#define SMEM_STRIDE 36
#define BUF_FLOATS  (128 * SMEM_STRIDE)
#define GEMM_SMEM   (4 * BUF_FLOATS * 4)   // 73728 B

__device__ __forceinline__ void gemm_issue(
    const float* __restrict__ A, const float* __restrict__ B,
    int m0, int n0, int c, int buf, uint32_t sb, int r0, int c4)
{
    const float* Ap = A + (size_t)(m0 + r0) * D_MODEL + c * 32 + c4;
    const float* Bp = B + (size_t)(n0 + r0) * D_MODEL + c * 32 + c4;
    uint32_t dA = sb + (uint32_t)((buf * BUF_FLOATS + r0 * SMEM_STRIDE + c4) * 4);
    uint32_t dB = dA + 2 * BUF_FLOATS * 4;
    #pragma unroll
    for (int i = 0; i < 4; i++) {
        cp16(dA + i * (32 * SMEM_STRIDE * 4), Ap + (size_t)i * 32 * D_MODEL);
        cp16(dB + i * (32 * SMEM_STRIDE * 4), Bp + (size_t)i * 32 * D_MODEL);
    }
}

__device__ __forceinline__ void gemm_cp(
    const float* __restrict__ A, const float* __restrict__ B,
    int m0, int n0, float acc[4][4][4])
{
    extern __shared__ float smf[];
    const uint32_t sb = smem_u32(smf);
    const int tid = threadIdx.x, lane = tid & 31, wid = tid >> 5;
    const int warp_m = wid >> 2, warp_n = wid & 3;
    const int r0 = tid >> 3, c4 = (tid & 7) * 4;

    #pragma unroll
    for (int mi = 0; mi < 4; mi++)
        #pragma unroll
        for (int ni = 0; ni < 4; ni++)
            #pragma unroll
            for (int r = 0; r < 4; r++) acc[mi][ni][r] = 0.0f;

    const int frow = (lane & 7) + ((lane >> 3) & 1) * 8;
    const int fcol = ((lane >> 4) & 1) * 4;
    const uint32_t aAddr = sb + (uint32_t)(((warp_m * 64 + frow) * SMEM_STRIDE + fcol) * 4);
    const uint32_t bAddr = sb + (uint32_t)(2 * BUF_FLOATS * 4)
                         + (uint32_t)(((warp_n * 32 + (lane & 7)) * SMEM_STRIDE + (lane >> 3) * 4) * 4);

    gemm_issue(A, B, m0, n0, 0, 0, sb, r0, c4);
    CP_COMMIT();

    #pragma unroll 1
    for (int c = 0; c < 32; c++) {
        CP_WAIT0();
        __syncthreads();
        if (c + 1 < 32) {
            gemm_issue(A, B, m0, n0, c + 1, (c + 1) & 1, sb, r0, c4);
            CP_COMMIT();
        }
        const uint32_t ab = aAddr + (uint32_t)((c & 1) * BUF_FLOATS * 4);
        const uint32_t bb = bAddr + (uint32_t)((c & 1) * BUF_FLOATS * 4);

        #pragma unroll
        for (int kp = 0; kp < 2; kp++) {
            uint32_t bfr[4][4], af0[4][4], af1[4][4];
            #pragma unroll
            for (int ni = 0; ni < 4; ni++)
                ldsm4(bfr[ni], bb + (uint32_t)((ni * 8 * SMEM_STRIDE + kp * 16) * 4));
            #pragma unroll
            for (int mi = 0; mi < 4; mi++) {
                ldsm4(af0[mi], ab + (uint32_t)((mi * 16 * SMEM_STRIDE + kp * 16) * 4));
                ldsm4(af1[mi], ab + (uint32_t)((mi * 16 * SMEM_STRIDE + kp * 16 + 8) * 4));
            }
            #pragma unroll
            for (int mi = 0; mi < 4; mi++)
                #pragma unroll
                for (int ni = 0; ni < 4; ni++) {
                    mma_m16n8k8(acc[mi][ni], af0[mi], bfr[ni]);
                    mma_m16n8k8(acc[mi][ni], af1[mi], bfr[ni] + 2);
                }
        }
    }
}

// ============================================================================
// QKV projection: Y = X @ W^T + b, tf32-rounded.
// Q,K -> head-major [B,H,S,dk];  V -> TRANSPOSED head-major [B,H,dk,S].
// ============================================================================
__global__ __launch_bounds__(256, 2) void qkv_tc_kernel(
    const float* __restrict__ bq, const float* __restrict__ bk, const float* __restrict__ bv)
{
    const int z = blockIdx.z;
    const float* A = g_X32 + (size_t)z * TOKENS * D_MODEL;
    const float* B = g_W32 + (size_t)z * D_MODEL * D_MODEL;
    const float* bias = (z == 0) ? bq : (z == 1) ? bk : bv;
    float* Y = (z == 0) ? g_Qh : (z == 1) ? g_Kh : g_Vh;

    const int m0 = blockIdx.y * 128;
    const int n0 = blockIdx.x * 128;

    float acc[4][4][4];
    gemm_cp(A, B, m0, n0, acc);

    const int tid = threadIdx.x, lane = tid & 31, wid = tid >> 5;
    const int warp_m = wid >> 2, warp_n = wid & 3;
    const int h = (n0 + warp_n * 32) >> 6;

    if (z < 2) {
        #pragma unroll
        for (int mi = 0; mi < 4; mi++) {
            int m_lo = m0 + warp_m * 64 + mi * 16 + (lane >> 2);
            int m_hi = m_lo + 8;
            float* row_lo = Y + (((size_t)(m_lo >> 11) * NHEAD + h) * SEQ + (m_lo & 2047)) * DK;
            float* row_hi = Y + (((size_t)(m_hi >> 11) * NHEAD + h) * SEQ + (m_hi & 2047)) * DK;
            #pragma unroll
            for (int ni = 0; ni < 4; ni++) {
                int colg = n0 + warp_n * 32 + ni * 8 + (lane & 3) * 2;
                float2 bb = *(const float2*)&bias[colg];
                int dkc = colg & 63;
                *(float2*)&row_lo[dkc] = make_float2(tf32r(acc[mi][ni][0] + bb.x), tf32r(acc[mi][ni][1] + bb.y));
                *(float2*)&row_hi[dkc] = make_float2(tf32r(acc[mi][ni][2] + bb.x), tf32r(acc[mi][ni][3] + bb.y));
            }
        }
    } else {
        // V transposed: [B,H,dk,S]. 8-lane quad-columns write 32B sectors.
        #pragma unroll
        for (int mi = 0; mi < 4; mi++) {
            int m_lo = m0 + warp_m * 64 + mi * 16 + (lane >> 2);
            int b_i = m_lo >> 11;
            int s_lo = m_lo & 2047, s_hi = s_lo + 8;
            float* vb0 = Y + ((size_t)b_i * NHEAD + h) * DK * SEQ;
            #pragma unroll
            for (int ni = 0; ni < 4; ni++) {
                int colg = n0 + warp_n * 32 + ni * 8 + (lane & 3) * 2;
                float2 bb = *(const float2*)&bias[colg];
                int dkc = colg & 63;
                float* r0p = vb0 + (size_t)dkc * SEQ;
                float* r1p = r0p + SEQ;
                r0p[s_lo] = tf32r(acc[mi][ni][0] + bb.x);
                r1p[s_lo] = tf32r(acc[mi][ni][1] + bb.y);
                r0p[s_hi] = tf32r(acc[mi][ni][2] + bb.x);
                r1p[s_hi] = tf32r(acc[mi][ni][3] + bb.y);
            }
        }
    }
}

// ============================================================================
// Output projection: out = ctx @ Wo^T + bo  (final output: full fp32)
// ============================================================================
__global__ __launch_bounds__(256, 2) void out_tc_kernel(
    const float* __restrict__ bo, float* __restrict__ out)
{
    const int m0 = blockIdx.y * 128;
    const int n0 = blockIdx.x * 128;

    float acc[4][4][4];
    gemm_cp(g_ctx, g_W32 + (size_t)3 * D_MODEL * D_MODEL, m0, n0, acc);

    const int tid = threadIdx.x, lane = tid & 31, wid = tid >> 5;
    const int warp_m = wid >> 2, warp_n = wid & 3;

    #pragma unroll
    for (int mi = 0; mi < 4; mi++) {
        int m_lo = m0 + warp_m * 64 + mi * 16 + (lane >> 2);
        float* row_lo = out + (size_t)m_lo * D_MODEL;
        float* row_hi = row_lo + 8 * D_MODEL;
        #pragma unroll
        for (int ni = 0; ni < 4; ni++) {
            int colg = n0 + warp_n * 32 + ni * 8 + (lane & 3) * 2;
            float2 bb = *(const float2*)&bo[colg];
            *(float2*)&row_lo[colg] = make_float2(acc[mi][ni][0] + bb.x, acc[mi][ni][1] + bb.y);
            *(float2*)&row_hi[colg] = make_float2(acc[mi][ni][2] + bb.x, acc[mi][ni][3] + bb.y);
        }
    }
}

// ============================================================================
// Flash attention, tf32 mma.sync + ldmatrix, fat 32qx64k warp tiles.
// Block = 128 queries of one (b,h), 4 warps. V is pre-transposed in gmem ->
// both K and V arrive via cp.async double-buffer (one commit group).
// ONE block barrier per tile; P is warp-private (syncwarp only).
// ============================================================================
#define AST 68
#define ATTN_SMEM ((128 + 128 + 128) * AST * 4)   // P/Q, K x2, Vt x2 = 104448 B

__global__ __launch_bounds__(128, 2) void attn_tc_kernel()
{
    extern __shared__ float sm[];
    float* Ps = sm;                  // [128][AST] — Q staging, then P tiles
    // Ks: 2 x [64][AST] at sm + 128*AST ; Vt: 2 x [64][AST] at sm + 256*AST

    const int tid = threadIdx.x, lane = tid & 31, wid = tid >> 5;   // wid 0..3
    const int bh = blockIdx.y, q0 = blockIdx.x * 128;
    const uint32_t sb = smem_u32(sm);

    const float* Qb = g_Qh + ((size_t)bh * SEQ + q0) * DK;
    const float* Kb = g_Kh + (size_t)bh * SEQ * DK;
    const float* Vb = g_Vh + (size_t)bh * DK * SEQ;   // [dk][S]

    // ---- Q -> smem, scaled by (1/sqrt(dk)) * log2(e)
    const float QSCALE = 0.18033688011112042f;
    #pragma unroll
    for (int it = 0; it < 16; it++) {
        int idx = tid + it * 128;
        int row = idx >> 4, c4 = (idx & 15) * 4;
        float4 t = *(const float4*)&Qb[(size_t)row * DK + c4];
        *(float4*)&Ps[row * AST + c4] =
            make_float4(tf32r(t.x * QSCALE), tf32r(t.y * QSCALE), tf32r(t.z * QSCALE), tf32r(t.w * QSCALE));
    }

    // ---- cp.async mappings: row = tid>>1 (0..63), col-half = (tid&1)*32 floats
    const int crow = tid >> 1, ccol = (tid & 1) * 32;
    const uint32_t kDst0 = sb + (uint32_t)((128 * AST + crow * AST + ccol) * 4);
    const uint32_t vDst0 = sb + (uint32_t)((256 * AST + crow * AST + ccol) * 4);

    // ---- issue K(0), V(0)
    {
        const float* ks = Kb + (size_t)crow * DK + ccol;
        const float* vs = Vb + (size_t)crow * SEQ + ccol;
        #pragma unroll
        for (int i = 0; i < 8; i++) cp16(kDst0 + i * 16, ks + i * 4);
        #pragma unroll
        for (int i = 0; i < 8; i++) cp16(vDst0 + i * 16, vs + i * 4);
        CP_COMMIT();
    }
    __syncthreads();

    // ---- Q fragments -> registers (loop-invariant): 2 m-frags x 8 k-frags
    const int frow = (lane & 7) + ((lane >> 3) & 1) * 8;
    const int fcol = ((lane >> 4) & 1) * 4;
    const uint32_t pAddr = sb + (uint32_t)(((wid * 32 + frow) * AST + fcol) * 4);
    uint32_t qf[2][8][4];
    #pragma unroll
    for (int mi = 0; mi < 2; mi++)
        #pragma unroll
        for (int ki = 0; ki < 8; ki++)
            ldsm4(qf[mi][ki], pAddr + (uint32_t)(mi * 16 * AST * 4) + ki * 32);

    const uint32_t kAddr = sb + (uint32_t)((128 * AST + (lane & 7) * AST + (lane >> 3) * 4) * 4);
    const uint32_t vAddr = sb + (uint32_t)((256 * AST + (lane & 7) * AST + (lane >> 3) * 4) * 4);

    float o[2][8][4];
    float m_i[4] = {-1e30f, -1e30f, -1e30f, -1e30f};
    float l_i[4] = {0.0f, 0.0f, 0.0f, 0.0f};
    #pragma unroll
    for (int mi = 0; mi < 2; mi++)
        #pragma unroll
        for (int ni = 0; ni < 8; ni++)
            #pragma unroll
            for (int r = 0; r < 4; r++) o[mi][ni][r] = 0.0f;

    float* wP = Ps + (wid * 32 + (lane >> 2)) * AST + (lane & 3) * 2;

    #pragma unroll 1
    for (int t = 0; t < 32; t++) {
        CP_WAIT0();
        __syncthreads();    // K(t),V(t) resident; prior-iter reads of the other bufs done

        // issue K(t+1), V(t+1) into the other buffers
        if (t + 1 < 32) {
            uint32_t boff = (uint32_t)(((t + 1) & 1) * 64 * AST * 4);
            const float* ks = Kb + (size_t)((t + 1) * 64 + crow) * DK + ccol;
            const float* vs = Vb + (size_t)crow * SEQ + (t + 1) * 64 + ccol;
            #pragma unroll
            for (int i = 0; i < 8; i++) cp16(kDst0 + boff + i * 16, ks + i * 4);
            #pragma unroll
            for (int i = 0; i < 8; i++) cp16(vDst0 + boff + i * 16, vs + i * 4);
            CP_COMMIT();
        }

        // ---- S = Q K^T (warp tile 32 x 64): 4 MMAs per K ldsm4
        const uint32_t kb = kAddr + (uint32_t)((t & 1) * 64 * AST * 4);
        float s[2][8][4];
        #pragma unroll
        for (int mi = 0; mi < 2; mi++)
            #pragma unroll
            for (int ni = 0; ni < 8; ni++)
                #pragma unroll
                for (int r = 0; r < 4; r++) s[mi][ni][r] = 0.0f;

        #pragma unroll
        for (int ni = 0; ni < 8; ni++) {
            #pragma unroll
            for (int kp = 0; kp < 4; kp++) {
                uint32_t b4[4];
                ldsm4(b4, kb + (uint32_t)((ni * 8 * AST + kp * 16) * 4));
                mma_m16n8k8(s[0][ni], qf[0][2 * kp],     b4);
                mma_m16n8k8(s[0][ni], qf[0][2 * kp + 1], b4 + 2);
                mma_m16n8k8(s[1][ni], qf[1][2 * kp],     b4);
                mma_m16n8k8(s[1][ni], qf[1][2 * kp + 1], b4 + 2);
            }
        }

        // ---- online softmax, 4 row-groups
        #pragma unroll
        for (int mi = 0; mi < 2; mi++) {
            #pragma unroll
            for (int r2 = 0; r2 < 2; r2++) {
                const int rg = mi * 2 + r2;
                float mx = -1e30f;
                #pragma unroll
                for (int ni = 0; ni < 8; ni++)
                    mx = fmaxf(mx, fmaxf(s[mi][ni][2 * r2], s[mi][ni][2 * r2 + 1]));
                mx = fmaxf(mx, __shfl_xor_sync(0xffffffffu, mx, 1));
                mx = fmaxf(mx, __shfl_xor_sync(0xffffffffu, mx, 2));
                float mnew = fmaxf(m_i[rg], mx);
                float corr = exp2f(m_i[rg] - mnew);
                float rs = 0.0f;
                #pragma unroll
                for (int ni = 0; ni < 8; ni++) {
                    float p0 = exp2f(s[mi][ni][2 * r2]     - mnew);
                    float p1 = exp2f(s[mi][ni][2 * r2 + 1] - mnew);
                    rs += p0 + p1;
                    *(float2*)&wP[(mi * 16 + r2 * 8) * AST + ni * 8] = make_float2(tf32r(p0), tf32r(p1));
                }
                rs += __shfl_xor_sync(0xffffffffu, rs, 1);
                rs += __shfl_xor_sync(0xffffffffu, rs, 2);
                l_i[rg] = l_i[rg] * corr + rs;
                m_i[rg] = mnew;
                #pragma unroll
                for (int ni = 0; ni < 8; ni++) {
                    o[mi][ni][2 * r2]     *= corr;
                    o[mi][ni][2 * r2 + 1] *= corr;
                }
            }
        }
        __syncwarp();   // P rows are warp-private; warp-scope visibility suffices

        // ---- O += P @ V^T : 4 MMAs per V ldsm4
        const uint32_t vb = vAddr + (uint32_t)((t & 1) * 64 * AST * 4);
        uint32_t pf[2][8][4];
        #pragma unroll
        for (int mi = 0; mi < 2; mi++)
            #pragma unroll
            for (int ki = 0; ki < 8; ki++)
                ldsm4(pf[mi][ki], pAddr + (uint32_t)(mi * 16 * AST * 4) + ki * 32);
        #pragma unroll
        for (int ni = 0; ni < 8; ni++) {
            #pragma unroll
            for (int kp = 0; kp < 4; kp++) {
                uint32_t b4[4];
                ldsm4(b4, vb + (uint32_t)((ni * 8 * AST + kp * 16) * 4));
                mma_m16n8k8(o[0][ni], pf[0][2 * kp],     b4);
                mma_m16n8k8(o[0][ni], pf[0][2 * kp + 1], b4 + 2);
                mma_m16n8k8(o[1][ni], pf[1][2 * kp],     b4);
                mma_m16n8k8(o[1][ni], pf[1][2 * kp + 1], b4 + 2);
            }
        }
    }

    // ---- epilogue: normalize, tf32-round, write to g_ctx[B,S,D]
    const int b_idx = bh >> 4;
    const int hh    = bh & 15;
    #pragma unroll
    for (int mi = 0; mi < 2; mi++) {
        #pragma unroll
        for (int r2 = 0; r2 < 2; r2++) {
            const int rg = mi * 2 + r2;
            float inv = 1.0f / l_i[rg];
            int row = q0 + wid * 32 + mi * 16 + r2 * 8 + (lane >> 2);
            float* dst = g_ctx + ((size_t)b_idx * SEQ + row) * D_MODEL + hh * DK;
            #pragma unroll
            for (int ni = 0; ni < 8; ni++) {
                int col = ni * 8 + (lane & 3) * 2;
                *(float2*)&dst[col] = make_float2(tf32r(o[mi][ni][2 * r2] * inv),
                                                  tf32r(o[mi][ni][2 * r2 + 1] * inv));
            }
        }
    }
}

// ============================================================================
// Launch
// ============================================================================
extern "C" void kernel_launch(void* const* d_in, const int* in_sizes, int n_in,
                              void* d_out, int out_size)
{
    const float* q  = (const float*)d_in[0];
    const float* k  = (const float*)d_in[1];
    const float* v  = (const float*)d_in[2];
    const float* Wq = (const float*)d_in[3];
    const float* bq = (const float*)d_in[4];
    const float* Wk = (const float*)d_in[5];
    const float* bk = (const float*)d_in[6];
    const float* Wv = (const float*)d_in[7];
    const float* bv = (const float*)d_in[8];
    const float* Wo = (const float*)d_in[9];
    const float* bo = (const float*)d_in[10];
    float* out = (float*)d_out;

    cudaFuncSetAttribute(qkv_tc_kernel,  cudaFuncAttributeMaxDynamicSharedMemorySize, GEMM_SMEM);
    cudaFuncSetAttribute(out_tc_kernel,  cudaFuncAttributeMaxDynamicSharedMemorySize, GEMM_SMEM);
    cudaFuncSetAttribute(attn_tc_kernel, cudaFuncAttributeMaxDynamicSharedMemorySize, ATTN_SMEM);

    dim3 gcvt(296, 7);
    cvt_tf32_kernel<<<gcvt, 256>>>(q, k, v, Wq, Wk, Wv, Wo);

    dim3 gqkv(D_MODEL / 128, TOKENS / 128, 3);
    qkv_tc_kernel<<<gqkv, 256, GEMM_SMEM>>>(bq, bk, bv);

    dim3 gattn(SEQ / 128, BATCH * NHEAD);
    attn_tc_kernel<<<gattn, 128, ATTN_SMEM>>>();

    dim3 gout(D_MODEL / 128, TOKENS / 128);
    out_tc_kernel<<<gout, 256, GEMM_SMEM>>>(bo, out);
}